// round 4
// baseline (speedup 1.0000x reference)
#include <cuda_runtime.h>
#include <stdint.h>

// ---------------- constants ----------------
#define MAXN_LAB (1 << 18)          // label scratch capacity (N = 200000 fits)
#define MAXC     128                // per-warp shared accumulator capacity
#define JW       5632               // columns per main-pass chunk (11 groups of 512)
#define NSEED    8192               // columns handled exactly by the seed pass
#define SEEDSPLIT 4                 // blocks per row in the seed pass
#define ENC_NINF ((int)0x807FFFFF)  // order-preserving encoding of -inf

// ---------------- device scratch (static: no allocation) ----------------
__device__ unsigned char g_lab[MAXN_LAB + 8];
__device__ int g_is64;

// Order-preserving float<->int bijection (self-inverse, monotone for non-NaN).
__device__ __forceinline__ int enc_f(float f) {
    int i = __float_as_int(f);
    return (i >= 0) ? i : (i ^ 0x7fffffff);
}
__device__ __forceinline__ float dec_i(int i) {
    return __int_as_float((i >= 0) ? i : (i ^ 0x7fffffff));
}

// ---------------- kernel 0: init output + dtype flag ----------------
__global__ void smp_init(int* __restrict__ out_enc, int BC) {
    int i = blockIdx.x * blockDim.x + threadIdx.x;
    if (i < BC) out_enc[i] = ENC_NINF;
    if (i == 0) g_is64 = 1;
}

// ---------------- kernel 1: detect label width ----------------
// int64 labels in [0,C) have every odd int32 word == 0 (little endian).
__global__ void smp_detect(const int* __restrict__ l32, int N) {
    int i = blockIdx.x * blockDim.x + threadIdx.x;
    if (i < N && (i & 1) && l32[i] != 0) g_is64 = 0;  // racy same-value store: fine
}

// ---------------- kernel 2: compact labels -> uint8 ----------------
__global__ void smp_compact(const void* __restrict__ labels, int N) {
    int i = blockIdx.x * blockDim.x + threadIdx.x;
    if (i < N) {
        int v = g_is64 ? (int)((const long long*)labels)[i]
                       : ((const int*)labels)[i];
        g_lab[i] = (unsigned char)v;
    }
}

// ---------------- kernel 3: seed pass -----------------------------------
// Exact stratified max over columns [0, NS). Grid (B, SEEDSPLIT). Per-block
// shared accumulator (encoded ints) merged into the output with atomicMax.
// Gives every (row, class) a real sample max so the main pass can use a
// tight scalar threshold.
__global__ __launch_bounds__(256) void smp_seed(
    const float* __restrict__ vals, int* __restrict__ out_enc,
    int B, int N, int C, int NS)
{
    __shared__ int sacc[MAXC];
    const int row  = blockIdx.x;
    const int part = blockIdx.y;
    const int tid  = threadIdx.x;

    for (int c = tid; c < MAXC; c += 256) sacc[c] = ENC_NINF;
    __syncthreads();

    const int per = (NS / SEEDSPLIT) & ~3;              // 4-aligned split
    const int s   = part * per;
    const int e   = (part == SEEDSPLIT - 1) ? NS : s + per;
    const float* rowp = vals + (size_t)row * N;

    // float4 bulk
    const int s4 = s >> 2, e4 = e >> 2;
    for (int i = s4 + tid; i < e4; i += 256) {
        float4 v = ((const float4*)rowp)[i];
        unsigned lw = ((const unsigned*)g_lab)[i];
        int c0 =  lw        & 0xff, c1 = (lw >> 8) & 0xff;
        int c2 = (lw >> 16) & 0xff, c3 =  lw >> 24;
        int e0 = enc_f(v.x); if (e0 > sacc[c0]) atomicMax(&sacc[c0], e0);
        int e1 = enc_f(v.y); if (e1 > sacc[c1]) atomicMax(&sacc[c1], e1);
        int e2 = enc_f(v.z); if (e2 > sacc[c2]) atomicMax(&sacc[c2], e2);
        int e3 = enc_f(v.w); if (e3 > sacc[c3]) atomicMax(&sacc[c3], e3);
    }
    // scalar tail (only if NS % 4 != 0)
    for (int j = (e4 << 2) + tid; j < e; j += 256) {
        int c = g_lab[j];
        int ev = enc_f(rowp[j]);
        if (ev > sacc[c]) atomicMax(&sacc[c], ev);
    }
    __syncthreads();

    int* orow = out_enc + row * C;
    for (int c = tid; c < C; c += 256)
        if (sacc[c] != ENC_NINF) atomicMax(orow + c, sacc[c]);
}

// ---------------- slow path for the main pass ----------------------------
__device__ __forceinline__ void slow4(float4 v, int col, float tmin,
                                      float* __restrict__ acc,
                                      int* __restrict__ orow)
{
    if (v.x > tmin) { int c = g_lab[col + 0]; if (v.x > acc[c]) { acc[c] = v.x; atomicMax(orow + c, enc_f(v.x)); } }
    if (v.y > tmin) { int c = g_lab[col + 1]; if (v.y > acc[c]) { acc[c] = v.y; atomicMax(orow + c, enc_f(v.y)); } }
    if (v.z > tmin) { int c = g_lab[col + 2]; if (v.z > acc[c]) { acc[c] = v.z; atomicMax(orow + c, enc_f(v.z)); } }
    if (v.w > tmin) { int c = g_lab[col + 3]; if (v.w > acc[c]) { acc[c] = v.w; atomicMax(orow + c, enc_f(v.w)); } }
}

// ---------------- kernel 4: main streaming max over [NS, N) ---------------
// Grid (ceil((N-NS)/JW), ceil(B/8)), 256 threads (8 warps, one row each).
// Hot path: 4 batched float4 loads per lane (MLP=4), 15 FMNMX, 1 compare
// against the scalar register threshold tmin. No labels, no shared in the
// hot path. Slow path (~5% of elements) consults the per-warp shared cache;
// global atomicMax on encoded ints is the sole authoritative merge.
__global__ __launch_bounds__(256) void smp_main(
    const float* __restrict__ vals, int* __restrict__ out_enc,
    int B, int N, int C, int j0base)
{
    __shared__ float accs[8][MAXC];
    const int tid  = threadIdx.x;
    const int w    = tid >> 5;
    const int lane = tid & 31;
    const int row  = blockIdx.y * 8 + w;
    if (row >= B) return;
    const int j0 = j0base + blockIdx.x * JW;
    if (j0 >= N) return;
    const int n  = min(JW, N - j0);

    int* orow  = out_enc + row * C;
    float* acc = accs[w];

    // Seed the per-warp cache from the (already exact-over-[0,NS)) output and
    // derive the scalar filter threshold tmin = min_c seeded[c].
    float tmin = __int_as_float(0x7f800000);   // +inf
    for (int c = lane; c < C; c += 32) {
        float a = dec_i(orow[c]);
        acc[c] = a;
        tmin = fminf(tmin, a);
    }
    #pragma unroll
    for (int off = 16; off; off >>= 1)
        tmin = fminf(tmin, __shfl_xor_sync(0xffffffffu, tmin, off));
    __syncwarp();

    const float4* rp = (const float4*)(vals + (size_t)row * N + j0);
    const int n4 = n >> 2;
    const int ng = n4 >> 7;                    // groups of 128 words = 512 cols

    for (int g = 0; g < ng; g++) {
        const int base = (g << 7) + lane;
        float4 a  = rp[base];
        float4 b  = rp[base + 32];
        float4 c4 = rp[base + 64];
        float4 d  = rp[base + 96];
        float m0 = fmaxf(fmaxf(a.x,  a.y),  fmaxf(a.z,  a.w));
        float m1 = fmaxf(fmaxf(b.x,  b.y),  fmaxf(b.z,  b.w));
        float m2 = fmaxf(fmaxf(c4.x, c4.y), fmaxf(c4.z, c4.w));
        float m3 = fmaxf(fmaxf(d.x,  d.y),  fmaxf(d.z,  d.w));
        float mg = fmaxf(fmaxf(m0, m1), fmaxf(m2, m3));
        if (mg > tmin) {
            int col = j0 + (base << 2);
            if (m0 > tmin) slow4(a,  col,       tmin, acc, orow);
            if (m1 > tmin) slow4(b,  col + 128, tmin, acc, orow);
            if (m2 > tmin) slow4(c4, col + 256, tmin, acc, orow);
            if (m3 > tmin) slow4(d,  col + 384, tmin, acc, orow);
        }
    }
    // remainder float4s
    for (int i = (ng << 7) + lane; i < n4; i += 32) {
        float4 a = rp[i];
        float m = fmaxf(fmaxf(a.x, a.y), fmaxf(a.z, a.w));
        if (m > tmin) slow4(a, j0 + (i << 2), tmin, acc, orow);
    }
    // scalar tail (only if n % 4 != 0)
    const int tail = n & 3;
    if (lane < tail) {
        int col = j0 + (n4 << 2) + lane;
        float v = vals[(size_t)row * N + col];
        if (v > tmin) {
            int c = g_lab[col];
            if (v > acc[c]) atomicMax(orow + c, enc_f(v));
        }
    }
}

// ---------------- fallback: fully general (C > MAXC or N > MAXN_LAB) ------
__global__ void smp_naive(const float* __restrict__ vals, const void* __restrict__ labels,
                          int* __restrict__ out_enc, int B, int N, int C)
{
    long long total  = (long long)B * N;
    long long stride = (long long)gridDim.x * blockDim.x;
    int is64 = g_is64;
    for (long long idx = blockIdx.x * (long long)blockDim.x + threadIdx.x;
         idx < total; idx += stride) {
        int j = (int)(idx % N);
        int b = (int)(idx / N);
        int c = is64 ? (int)((const long long*)labels)[j]
                     : ((const int*)labels)[j];
        atomicMax(out_enc + b * C + c, enc_f(vals[idx]));
    }
}

// ---------------- kernel 5: decode in place ----------------
__global__ void smp_fin(int* __restrict__ io, int BC) {
    int i = blockIdx.x * blockDim.x + threadIdx.x;
    if (i < BC) {
        int e = io[i];
        io[i] = (e >= 0) ? e : (e ^ 0x7fffffff);
    }
}

// ---------------- launch ----------------
extern "C" void kernel_launch(void* const* d_in, const int* in_sizes, int n_in,
                              void* d_out, int out_size)
{
    const float* vals   = (const float*)d_in[0];
    const void*  labels = d_in[1];

    const int NV = in_sizes[0];      // B * N
    const int N  = in_sizes[1];      // 200000
    const int B  = NV / N;           // 128
    const int BC = out_size;         // B * C
    const int C  = BC / B;           // 100
    int* out_enc = (int*)d_out;

    const bool fast = (C <= MAXC) && (N <= MAXN_LAB) && ((size_t)B * N == (size_t)NV);

    int tmax = (N > BC) ? N : BC;
    smp_init  <<<(tmax + 255) / 256, 256>>>(out_enc, BC);
    smp_detect<<<(N + 255) / 256, 256>>>((const int*)labels, N);

    if (fast) {
        smp_compact<<<(N + 255) / 256, 256>>>(labels, N);

        const int NS = (N < NSEED) ? N : NSEED;
        if (NS > 0) {
            dim3 sg(B, SEEDSPLIT);
            smp_seed<<<sg, 256>>>(vals, out_enc, B, N, C, NS);
        }
        const int Nmain = N - NS;
        if (Nmain > 0) {
            dim3 grid((Nmain + JW - 1) / JW, (B + 7) / 8);
            smp_main<<<grid, 256>>>(vals, out_enc, B, N, C, NS);
        }
    } else {
        smp_naive<<<1184, 256>>>(vals, labels, out_enc, B, N, C);
    }

    smp_fin<<<(BC + 255) / 256, 256>>>(out_enc, BC);
}

// round 5
// speedup vs baseline: 1.2024x; 1.2024x over previous
#include <cuda_runtime.h>
#include <stdint.h>

// ---------------- constants ----------------
#define MAXN_LAB  (1 << 18)          // label scratch capacity (N = 200000 fits)
#define MAXC_FAST 108                // fast path: C*256*4 <= ~110KB (2 blocks/SM)
#define ENC_NINF  ((int)0x807FFFFF)  // order-preserving encoding of -inf
#define F_NINF    __int_as_float(0xff800000)

// ---------------- device scratch (static: no allocation) ----------------
__device__ unsigned char g_lab[MAXN_LAB + 16];
__device__ int g_is64;

// Order-preserving float<->int bijection (self-inverse, monotone for non-NaN).
__device__ __forceinline__ int enc_f(float f) {
    int i = __float_as_int(f);
    return (i >= 0) ? i : (i ^ 0x7fffffff);
}

// ---------------- kernel 0: init output + dtype flag ----------------
__global__ void smp_init(int* __restrict__ out_enc, int BC) {
    int i = blockIdx.x * blockDim.x + threadIdx.x;
    if (i < BC) out_enc[i] = ENC_NINF;
    if (i == 0) g_is64 = 1;
}

// ---------------- kernel 1: detect label width ----------------
// int64 labels in [0,C) have every odd int32 word == 0 (little endian).
__global__ void smp_detect(const int* __restrict__ l32, int N) {
    int i = blockIdx.x * blockDim.x + threadIdx.x;
    if (i < N && (i & 1) && l32[i] != 0) g_is64 = 0;  // racy same-value store: fine
}

// ---------------- kernel 2: compact labels -> uint8 ----------------
__global__ void smp_compact(const void* __restrict__ labels, int N) {
    int i = blockIdx.x * blockDim.x + threadIdx.x;
    if (i < N) {
        int v = g_is64 ? (int)((const long long*)labels)[i]
                       : ((const int*)labels)[i];
        g_lab[i] = (unsigned char)v;
    }
}

// ---------------- kernel 3: main streaming max ----------------------------
// Grid (ceil(N/JW), ceil(B/8)), 256 threads (8 warps; warp w owns one row).
// Lane-private accumulators: acc[c*256 + tid] is owned by exactly one thread.
//   - bank = (c*256 + tid) % 32 = lane  -> conflict-free for ANY label pattern
//   - single owner -> no races, no atomics, no branches in the hot loop
//   - same-thread may-alias smem ordering handles repeated classes in a quad
// Merge: per class, shfl-max across the warp's 32 lanes, one global atomicMax.
__global__ __launch_bounds__(256, 2) void smp_main(
    const float* __restrict__ vals, int* __restrict__ out_enc,
    int B, int N, int C, int JW)
{
    extern __shared__ float acc[];          // [C][256]
    const int tid  = threadIdx.x;
    const int w    = tid >> 5;
    const int lane = tid & 31;
    const int row  = blockIdx.y * 8 + w;
    const int j0   = blockIdx.x * JW;

    // Init private cells. Disjoint per-thread ownership: no sync needed.
    #pragma unroll 4
    for (int c = 0; c < C; c++) acc[c * 256 + tid] = F_NINF;

    if (row < B && j0 < N) {
        const int n  = min(JW, N - j0);
        const int n4 = n >> 2;
        const float4*   rp = (const float4*)(vals + (size_t)row * N + j0);
        const unsigned* lw = (const unsigned*)g_lab + (j0 >> 2);

        // Hot loop: coalesced float4 + label-word stream, branch-free updates.
        #pragma unroll 4
        for (int i = lane; i < n4; i += 32) {
            float4   v = rp[i];
            unsigned L = lw[i];
            int c0 =  L        & 0xff;
            int c1 = (L >>  8) & 0xff;
            int c2 = (L >> 16) & 0xff;
            int c3 =  L >> 24;
            float* a0 = acc + c0 * 256 + tid; *a0 = fmaxf(*a0, v.x);
            float* a1 = acc + c1 * 256 + tid; *a1 = fmaxf(*a1, v.y);
            float* a2 = acc + c2 * 256 + tid; *a2 = fmaxf(*a2, v.z);
            float* a3 = acc + c3 * 256 + tid; *a3 = fmaxf(*a3, v.w);
        }
        // Scalar tail (n % 4 != 0).
        const int tail = n & 3;
        if (lane < tail) {
            int col = j0 + (n4 << 2) + lane;
            float v = vals[(size_t)row * N + col];
            int c = g_lab[col];
            float* a = acc + c * 256 + tid;
            *a = fmaxf(*a, v);
        }
    }
    // No __syncthreads: each thread merges only its own cells.

    if (row < B) {
        int* orow = out_enc + row * C;
        for (int c = 0; c < C; c++) {
            float m = acc[c * 256 + tid];
            #pragma unroll
            for (int off = 16; off; off >>= 1)
                m = fmaxf(m, __shfl_xor_sync(0xffffffffu, m, off));
            if (lane == 0 && m > F_NINF)
                atomicMax(orow + c, enc_f(m));
        }
    }
}

// ---------------- fallback: fully general (C > MAXC_FAST or N > MAXN_LAB) --
__global__ void smp_naive(const float* __restrict__ vals, const void* __restrict__ labels,
                          int* __restrict__ out_enc, int B, int N, int C)
{
    long long total  = (long long)B * N;
    long long stride = (long long)gridDim.x * blockDim.x;
    int is64 = g_is64;
    for (long long idx = blockIdx.x * (long long)blockDim.x + threadIdx.x;
         idx < total; idx += stride) {
        int j = (int)(idx % N);
        int b = (int)(idx / N);
        int c = is64 ? (int)((const long long*)labels)[j]
                     : ((const int*)labels)[j];
        atomicMax(out_enc + b * C + c, enc_f(vals[idx]));
    }
}

// ---------------- kernel 4: decode in place ----------------
__global__ void smp_fin(int* __restrict__ io, int BC) {
    int i = blockIdx.x * blockDim.x + threadIdx.x;
    if (i < BC) {
        int e = io[i];
        io[i] = (e >= 0) ? e : (e ^ 0x7fffffff);
    }
}

// ---------------- launch ----------------
extern "C" void kernel_launch(void* const* d_in, const int* in_sizes, int n_in,
                              void* d_out, int out_size)
{
    const float* vals   = (const float*)d_in[0];
    const void*  labels = d_in[1];

    const int NV = in_sizes[0];      // B * N
    const int N  = in_sizes[1];      // 200000
    const int B  = NV / N;           // 128
    const int BC = out_size;         // B * C
    const int C  = BC / B;           // 100
    int* out_enc = (int*)d_out;

    const bool fast = (C <= MAXC_FAST) && (N <= MAXN_LAB) &&
                      ((size_t)B * N == (size_t)NV);

    int tmax = (N > BC) ? N : BC;
    smp_init  <<<(tmax + 255) / 256, 256>>>(out_enc, BC);
    smp_detect<<<(N + 255) / 256, 256>>>((const int*)labels, N);

    if (fast) {
        smp_compact<<<(N + 255) / 256, 256>>>(labels, N);

        // Single wave: <= 296 resident blocks (2 per SM at ~100KB smem each).
        const size_t smem = (size_t)C * 256 * sizeof(float);
        static int smem_set = 0;
        if (!smem_set) {
            cudaFuncSetAttribute(smp_main,
                cudaFuncAttributeMaxDynamicSharedMemorySize, 113 * 1024);
            smem_set = 1;
        }
        int rowBlocks = (B + 7) / 8;              // 16
        int S = 296 / rowBlocks;                  // 18 column slices
        if (S < 1) S = 1;
        int JW = ((N + S - 1) / S + 3) & ~3;      // quad-aligned slice width
        dim3 grid((N + JW - 1) / JW, rowBlocks);
        smp_main<<<grid, 256, smem>>>(vals, out_enc, B, N, C, JW);
    } else {
        smp_naive<<<1184, 256>>>(vals, labels, out_enc, B, N, C);
    }

    smp_fin<<<(BC + 255) / 256, 256>>>(out_enc, BC);
}

// round 6
// speedup vs baseline: 1.3645x; 1.1348x over previous
#include <cuda_runtime.h>
#include <stdint.h>

// ---------------- constants ----------------
#define MAXN_LAB  (1 << 18)          // label scratch capacity (N = 200000 fits)
#define MAXC_FAST 108                // fast path: C*256*4 <= ~110KB (2 blocks/SM)
#define ENC_NINF  ((int)0x807FFFFF)  // order-preserving encoding of -inf
#define F_NINF    __int_as_float(0xff800000)

// ---------------- device scratch (static: no allocation) ----------------
__device__ int g_off[MAXN_LAB + 16];   // pre-scaled smem byte offsets: label*1024
__device__ int g_is64;

// Order-preserving float<->int bijection (self-inverse, monotone for non-NaN).
__device__ __forceinline__ int enc_f(float f) {
    int i = __float_as_int(f);
    return (i >= 0) ? i : (i ^ 0x7fffffff);
}

// ---------------- kernel 0: init output + dtype flag + width detect -------
// int64 labels in [0,C) have every odd int32 word == 0 (little endian).
__global__ void smp_init_detect(int* __restrict__ out_enc, int BC,
                                const int* __restrict__ l32, int N) {
    int i = blockIdx.x * blockDim.x + threadIdx.x;
    if (i == 0) g_is64 = 1;
    if (i < BC) out_enc[i] = ENC_NINF;
    if (i < N && (i & 1) && l32[i] != 0) g_is64 = 0;  // racy same-value store: fine
}

// ---------------- kernel 1: compact labels -> pre-scaled byte offsets -----
// offset = c * 1024  (acc stride per class = 256 threads * 4B)
__global__ void smp_compact(const void* __restrict__ labels, int N) {
    int i = blockIdx.x * blockDim.x + threadIdx.x;
    if (i < N) {
        int v = g_is64 ? (int)((const long long*)labels)[i]
                       : ((const int*)labels)[i];
        g_off[i] = v << 10;
    }
}

// ---------------- kernel 2: main streaming max ----------------------------
// Grid (slices, ceil(B/8)), 256 threads (8 warps; warp w owns one row).
// Lane-private accumulators acc[c*256 + tid]: conflict-free banks, single
// owner, no atomics. Hot loop per lane-quad:
//   - batched LDS x4 of stale cells (ONE latency window per 4 elements)
//   - branchless duplicate max-propagation in registers makes the batched
//     stale reads exact (last store to a duplicated address carries the max)
//   - register double-buffer prefetch of next quad (values via __ldcs)
__global__ __launch_bounds__(256, 2) void smp_main(
    const float* __restrict__ vals, int* __restrict__ out_enc,
    int B, int N, int C, int JW)
{
    extern __shared__ float acc[];          // [C][256]
    const int tid  = threadIdx.x;
    const int w    = tid >> 5;
    const int lane = tid & 31;
    const int row  = blockIdx.y * 8 + w;
    const int j0   = blockIdx.x * JW;

    // Init private cells. Disjoint ownership: no sync needed.
    #pragma unroll 4
    for (int c = 0; c < C; c++) acc[c * 256 + tid] = F_NINF;

    if (row < B && j0 < N) {
        const int n  = min(JW, N - j0);
        const int n4 = n >> 2;
        const float4* rp = (const float4*)(vals + (size_t)row * N + j0);
        const int4*   op = (const int4*)(g_off + j0);
        char* aB = (char*)acc + (tid << 2);

        int i = lane;
        float4 v; int4 o;
        bool any = (i < n4);
        if (any) { v = __ldcs(rp + i); o = op[i]; }
        while (any) {
            const int inext = i + 32;
            const bool more = (inext < n4);
            const int  ip   = more ? inext : i;        // clamped, in-bounds
            float4 vn = __ldcs(rp + ip);               // prefetch next quad
            int4   on = op[ip];

            float* a0 = (float*)(aB + o.x);
            float* a1 = (float*)(aB + o.y);
            float* a2 = (float*)(aB + o.z);
            float* a3 = (float*)(aB + o.w);
            // Batched stale reads: one LDS latency window per 4 elements.
            float s0 = *a0, s1 = *a1, s2 = *a2, s3 = *a3;
            // Duplicate-safe forward propagation (fills the LDS wait).
            if (o.x == o.y) v.y = fmaxf(v.y, v.x);
            if (o.x == o.z) v.z = fmaxf(v.z, v.x);
            if (o.y == o.z) v.z = fmaxf(v.z, v.y);
            if (o.x == o.w) v.w = fmaxf(v.w, v.x);
            if (o.y == o.w) v.w = fmaxf(v.w, v.y);
            if (o.z == o.w) v.w = fmaxf(v.w, v.z);
            // Stores in order: last store to a duplicated address wins and
            // carries the propagated max -> exact.
            *a0 = fmaxf(s0, v.x);
            *a1 = fmaxf(s1, v.y);
            *a2 = fmaxf(s2, v.z);
            *a3 = fmaxf(s3, v.w);

            v = vn; o = on; i = inext; any = more;
        }
        // Scalar tail (n % 4 != 0).
        const int tail = n & 3;
        if (lane < tail) {
            int col = j0 + (n4 << 2) + lane;
            float x = vals[(size_t)row * N + col];
            float* a = (float*)(aB + g_off[col]);
            *a = fmaxf(*a, x);
        }
    }
    // No __syncthreads: each thread merges only its own cells.

    if (row < B) {
        int* orow = out_enc + row * C;
        for (int c = 0; c < C; c++) {
            float m = acc[c * 256 + tid];
            #pragma unroll
            for (int off = 16; off; off >>= 1)
                m = fmaxf(m, __shfl_xor_sync(0xffffffffu, m, off));
            if (lane == 0 && m > F_NINF)
                atomicMax(orow + c, enc_f(m));
        }
    }
}

// ---------------- fallback: fully general (C > MAXC_FAST or N > MAXN_LAB) --
__global__ void smp_naive(const float* __restrict__ vals, const void* __restrict__ labels,
                          int* __restrict__ out_enc, int B, int N, int C)
{
    long long total  = (long long)B * N;
    long long stride = (long long)gridDim.x * blockDim.x;
    int is64 = g_is64;
    for (long long idx = blockIdx.x * (long long)blockDim.x + threadIdx.x;
         idx < total; idx += stride) {
        int j = (int)(idx % N);
        int b = (int)(idx / N);
        int c = is64 ? (int)((const long long*)labels)[j]
                     : ((const int*)labels)[j];
        atomicMax(out_enc + b * C + c, enc_f(vals[idx]));
    }
}

// ---------------- kernel 3: decode in place ----------------
__global__ void smp_fin(int* __restrict__ io, int BC) {
    int i = blockIdx.x * blockDim.x + threadIdx.x;
    if (i < BC) {
        int e = io[i];
        io[i] = (e >= 0) ? e : (e ^ 0x7fffffff);
    }
}

// ---------------- launch ----------------
extern "C" void kernel_launch(void* const* d_in, const int* in_sizes, int n_in,
                              void* d_out, int out_size)
{
    const float* vals   = (const float*)d_in[0];
    const void*  labels = d_in[1];

    const int NV = in_sizes[0];      // B * N
    const int N  = in_sizes[1];      // 200000
    const int B  = NV / N;           // 128
    const int BC = out_size;         // B * C
    const int C  = BC / B;           // 100
    int* out_enc = (int*)d_out;

    const bool fast = (C <= MAXC_FAST) && (N <= MAXN_LAB) &&
                      ((size_t)B * N == (size_t)NV);

    int tmax = (N > BC) ? N : BC;
    smp_init_detect<<<(tmax + 255) / 256, 256>>>(out_enc, BC, (const int*)labels, N);

    if (fast) {
        smp_compact<<<(N + 255) / 256, 256>>>(labels, N);

        // Single wave: <= 296 resident blocks (2 per SM at ~100KB smem each).
        const size_t smem = (size_t)C * 256 * sizeof(float);
        static int smem_set = 0;
        if (!smem_set) {
            cudaFuncSetAttribute(smp_main,
                cudaFuncAttributeMaxDynamicSharedMemorySize, 113 * 1024);
            smem_set = 1;
        }
        int rowBlocks = (B + 7) / 8;              // 16
        int S = 296 / rowBlocks;                  // 18 column slices
        if (S < 1) S = 1;
        int JW = ((N + S - 1) / S + 3) & ~3;      // quad-aligned slice width
        dim3 grid((N + JW - 1) / JW, rowBlocks);
        smp_main<<<grid, 256, smem>>>(vals, out_enc, B, N, C, JW);
    } else {
        smp_naive<<<1184, 256>>>(vals, labels, out_enc, B, N, C);
    }

    smp_fin<<<(BC + 255) / 256, 256>>>(out_enc, BC);
}